// round 7
// baseline (speedup 1.0000x reference)
#include <cuda_runtime.h>
#include <cuda_fp16.h>
#include <cstdint>

#define B_  4
#define S_  8192
#define D_  1024
#define H_  16
#define M_  (B_*S_)          // 32768
#define SCALE_ 0.125f
#define NSPLIT 16
#define SCHUNK (S_/NSPLIT)   // 512

// ---------------- scratch (device globals) ----------------
__device__ __half g_xh [(size_t)M_*D_];                    // x as fp16
__device__ __half g_Wqt_h[(size_t)D_*D_],   g_Wqt_l[(size_t)D_*D_];
__device__ __half g_Wkvt_h[(size_t)2*D_*D_], g_Wkvt_l[(size_t)2*D_*D_];
__device__ __half g_EQ [(size_t)M_*D_];                    // exp(Q logits)
__device__ __half g_Ykv[(size_t)M_*2*D_];                  // E=exp(K) | V (fp16)
__device__ __half g_Q  [(size_t)M_*D_];                    // normalized Q (fp16)
__device__ float g_zp[B_*H_*NSPLIT*64];
__device__ float g_Z [B_*H_*64];
__device__ float g_ctxp[(size_t)B_*H_*NSPLIT*64*64];
__device__ float g_ctx [B_*H_*64*64];
__device__ float g_W2[(size_t)B_*D_*D_];
__device__ __half g_W2t_h[(size_t)B_*D_*D_], g_W2t_l[(size_t)B_*D_*D_];

// ---------------- helpers ----------------
__device__ __forceinline__ uint32_t smem_u32(const void* p) {
    uint32_t a;
    asm("{ .reg .u64 t; cvta.to.shared.u64 t, %1; cvt.u32.u64 %0, t; }" : "=r"(a) : "l"(p));
    return a;
}
#define SWZ(off) ((off) ^ (((off) >> 3) & 0x70))

__device__ __forceinline__ void cpa16(uint32_t s, const void* g) {
    asm volatile("cp.async.cg.shared.global [%0], [%1], 16;" :: "r"(s), "l"(g));
}
#define CP_COMMIT() asm volatile("cp.async.commit_group;" ::: "memory")
#define CP_WAITG(n) asm volatile("cp.async.wait_group %0;" :: "n"(n) : "memory")

#define LDSM4(r, addr)                                                        \
    asm volatile("ldmatrix.sync.aligned.m8n8.x4.shared.b16 {%0,%1,%2,%3}, [%4];" \
        : "=r"((r)[0]), "=r"((r)[1]), "=r"((r)[2]), "=r"((r)[3]) : "r"(addr))

#define MMA16816(c, a, b0, b1)                                                \
    asm volatile("mma.sync.aligned.m16n8k16.row.col.f32.f16.f16.f32 "         \
        "{%0,%1,%2,%3},{%4,%5,%6,%7},{%8,%9},{%0,%1,%2,%3};"                  \
        : "+f"((c)[0]), "+f"((c)[1]), "+f"((c)[2]), "+f"((c)[3])              \
        : "r"((a)[0]), "r"((a)[1]), "r"((a)[2]), "r"((a)[3]),                 \
          "r"(b0), "r"(b1))

static constexpr int STAGE = 49152;           // A16K Bh16K Bl16K
static constexpr int SMEM_GEMM = 3 * STAGE;   // 144KB, 3-stage

// EPI modes: 0 = fp32 out + bias, 1 = fp16 exp(acc) all cols,
//            2 = fp16, exp(acc) only on K-columns ((n>>6)&1 == 0)
// ============================================================
// HMMA GEMM: C[M,N] = A[M,K] @ (Bh+Bl)[N,K]^T
// A single fp16; B split hi/lo fp16 (weights, effectively exact).
// CTA 128x128xK64, 8 warps (64x32), 3-stage cp.async, SW128 smem,
// single __syncthreads per chunk.
// ============================================================
template<int EPI>
__global__ __launch_bounds__(256, 1) void gemm_mma(
    const uint4* __restrict__ A,
    const uint4* __restrict__ Bh, const uint4* __restrict__ Bl,
    void* __restrict__ Cv, int M, int N, int K,
    size_t aBatch, size_t bBatch, size_t cBatch,
    const float* __restrict__ bias)
{
    extern __shared__ __align__(1024) char smem[];
    const uint32_t sbase = smem_u32(smem);
    const int tid = threadIdx.x, wid = tid >> 5, lane = tid & 31;
    const int bn = blockIdx.x * 128, bm = blockIdx.y * 128;
    const int z = blockIdx.z;
    A  += (size_t)z * aBatch;
    Bh += (size_t)z * bBatch; Bl += (size_t)z * bBatch;

    const int wm = (wid >> 2) * 64;
    const int wn = (wid & 3) * 32;
    const int Kq = K >> 3;

    const int lr = lane & 7, lq = lane >> 3;
    const uint32_t aRow = lr + (lq & 1) * 8,  aColB = (lq >> 1) * 16;
    const uint32_t bRow = lr + (lq >> 1) * 8, bColB = (lq & 1) * 16;

    float acc[4][4][4] = {};

    auto load_stage = [&](int s, int kq0) {
        uint32_t stb = sbase + s * STAGE;
#pragma unroll
        for (int ii = 0; ii < 4; ii++) {
            int i = tid + ii * 256;
            int r = i >> 3, cc = i & 7;
            uint32_t off = SWZ((uint32_t)(r * 128 + cc * 16));
            size_t gia = (size_t)(bm + r) * Kq + kq0 + cc;
            size_t gib = (size_t)(bn + r) * Kq + kq0 + cc;
            cpa16(stb + off,          A  + gia);
            cpa16(stb + 16384 + off,  Bh + gib);
            cpa16(stb + 32768 + off,  Bl + gib);
        }
    };

    const int nch = K >> 6;
    load_stage(0, 0);  CP_COMMIT();
    load_stage(1, 8);  CP_COMMIT();

    for (int c = 0; c < nch; ++c) {
        if (c + 1 < nch) { CP_WAITG(1); } else { CP_WAITG(0); }
        __syncthreads();
        if (c + 2 < nch) { load_stage((c + 2) % 3, (c + 2) * 8); CP_COMMIT(); }

        const uint32_t stb = sbase + (c % 3) * STAGE;
#pragma unroll
        for (int t = 0; t < 4; t++) {
            uint32_t a4[4][4], bh4[2][4], bl4[2][4];
#pragma unroll
            for (int mf = 0; mf < 4; mf++) {
                uint32_t off = SWZ((uint32_t)((wm + mf * 16 + aRow) * 128 + t * 32 + aColB));
                LDSM4(a4[mf], stb + off);
            }
#pragma unroll
            for (int p = 0; p < 2; p++) {
                uint32_t off = SWZ((uint32_t)((wn + p * 16 + bRow) * 128 + t * 32 + bColB));
                LDSM4(bh4[p], stb + 16384 + off);
                LDSM4(bl4[p], stb + 32768 + off);
            }
#pragma unroll
            for (int mf = 0; mf < 4; mf++)
#pragma unroll
                for (int nf = 0; nf < 4; nf++) {
                    int p = nf >> 1, hh = (nf & 1) * 2;
                    MMA16816(acc[mf][nf], a4[mf], bh4[p][hh], bh4[p][hh + 1]);
                    MMA16816(acc[mf][nf], a4[mf], bl4[p][hh], bl4[p][hh + 1]);
                }
        }
    }

    // epilogue
    const int g = lane >> 2, tt = lane & 3;
#pragma unroll
    for (int mf = 0; mf < 4; mf++)
#pragma unroll
        for (int nf = 0; nf < 4; nf++) {
            int m = bm + wm + mf * 16 + g;
            int n = bn + wn + nf * 8 + tt * 2;
            float v0 = acc[mf][nf][0], v1 = acc[mf][nf][1];
            float v2 = acc[mf][nf][2], v3 = acc[mf][nf][3];
            if constexpr (EPI == 0) {
                float b0 = bias[n], b1 = bias[n + 1];
                float* C = (float*)Cv + (size_t)z * cBatch;
                *(float2*)(C + (size_t)m * N + n)       = make_float2(v0 + b0, v1 + b1);
                *(float2*)(C + (size_t)(m + 8) * N + n) = make_float2(v2 + b0, v3 + b1);
            } else {
                bool doexp = (EPI == 1) || (((n >> 6) & 1) == 0);
                if (doexp) {
                    v0 = __expf(v0); v1 = __expf(v1);
                    v2 = __expf(v2); v3 = __expf(v3);
                }
                __half* C = (__half*)Cv + (size_t)z * cBatch;
                *(__half2*)(C + (size_t)m * N + n)       = __floats2half2_rn(v0, v1);
                *(__half2*)(C + (size_t)(m + 8) * N + n) = __floats2half2_rn(v2, v3);
            }
        }
}

// ============================================================
// x fp32 -> fp16 (elementwise)
// ============================================================
__global__ __launch_bounds__(256) void x_to_h(
    const float4* __restrict__ X, __half* __restrict__ O, size_t n4)
{
    size_t i = (size_t)blockIdx.x * 256 + threadIdx.x;
    if (i >= n4) return;
    float4 v = X[i];
    __half2* p = (__half2*)(O + i * 4);
    p[0] = __floats2half2_rn(v.x, v.y);
    p[1] = __floats2half2_rn(v.z, v.w);
}

// ============================================================
// W[K,N] -> transposed fp16 hi/lo [N,K]  (batched via z)
// ============================================================
__global__ __launch_bounds__(256) void transW_split(
    const float* __restrict__ W, __half* __restrict__ Th,
    __half* __restrict__ Tl, int K, int N)
{
    __shared__ float t[32][33];
    const size_t zoff = (size_t)blockIdx.z * K * N;
    W += zoff; Th += zoff; Tl += zoff;
    int n0 = blockIdx.x * 32, k0 = blockIdx.y * 32;
    int tx = threadIdx.x & 31, ty = threadIdx.x >> 5;
#pragma unroll
    for (int i = 0; i < 32; i += 8)
        t[ty + i][tx] = W[(size_t)(k0 + ty + i) * N + n0 + tx];
    __syncthreads();
#pragma unroll
    for (int i = 0; i < 32; i += 8) {
        float v = t[tx][ty + i];
        __half h = __float2half_rn(v);
        size_t o = (size_t)(n0 + ty + i) * K + k0 + tx;
        Th[o] = h;
        Tl[o] = __float2half_rn(v - __half2float(h));
    }
}

// ============================================================
// Q normalize (no exp — EQ already exponentiated):
// Q[w,:] = EQ[w,:] * SCALE / sum(EQ[w,:])   per (row,head) of 64
// ============================================================
__global__ __launch_bounds__(256) void qnorm(
    const __half2* __restrict__ EQ, __half2* __restrict__ Q)
{
    int w = (blockIdx.x * blockDim.x + threadIdx.x) >> 5;
    int lane = threadIdx.x & 31;
    float2 f = __half22float2(EQ[(size_t)w * 32 + lane]);
    float s = f.x + f.y;
#pragma unroll
    for (int o = 16; o; o >>= 1) s += __shfl_xor_sync(0xffffffffu, s, o);
    float inv = SCALE_ / s;
    Q[(size_t)w * 32 + lane] = __floats2half2_rn(f.x * inv, f.y * inv);
}

// ============================================================
// ctx partials (E already exponentiated in GEMM epilogue):
// ctxp[bh][sp][d][e] = sum_s E[s,d] * V[s,e];  zp = sum_s E[s,d]
// ============================================================
__global__ __launch_bounds__(256) void ctx_partial_kernel(
    const __half2* __restrict__ Ykv2, float* __restrict__ ctxp,
    float* __restrict__ zp)
{
    int bh = blockIdx.x, sp = blockIdx.y;
    int b = bh >> 4, h = bh & 15;
    int tid = threadIdx.x;
    __shared__ float Ek[8][64];
    __shared__ float Vt[8][64];
    int d = tid >> 2, q = tid & 3;
    float acc[16] = {};
    float zacc = 0.f;
    const __half2* base = Ykv2 + (size_t)(b * S_ + sp * SCHUNK) * 1024 + h * 64;
    for (int s0 = 0; s0 < SCHUNK; s0 += 8) {
#pragma unroll
        for (int i = 0; i < 2; i++) {
            int idx = tid + i * 256;
            int ss = idx >> 6, c2 = idx & 63;
            float2 f = __half22float2(base[(size_t)(s0 + ss) * 1024 + c2]);
            if (c2 < 32) { Ek[ss][2*c2] = f.x;    Ek[ss][2*c2+1] = f.y; }
            else         { Vt[ss][2*c2-64] = f.x; Vt[ss][2*c2-63] = f.y; }
        }
        __syncthreads();
#pragma unroll
        for (int ss = 0; ss < 8; ss++) {
            float ek = Ek[ss][d];
            if (q == 0) zacc += ek;
#pragma unroll
            for (int j4 = 0; j4 < 4; j4++) {
                float4 v = *(const float4*)&Vt[ss][q * 16 + j4 * 4];
                acc[j4*4+0] += ek * v.x; acc[j4*4+1] += ek * v.y;
                acc[j4*4+2] += ek * v.z; acc[j4*4+3] += ek * v.w;
            }
        }
        __syncthreads();
    }
    float* o = ctxp + ((size_t)bh * NSPLIT + sp) * 4096 + d * 64 + q * 16;
#pragma unroll
    for (int j4 = 0; j4 < 4; j4++)
        *(float4*)(o + j4 * 4) = make_float4(acc[j4*4], acc[j4*4+1], acc[j4*4+2], acc[j4*4+3]);
    if (q == 0) zp[(bh * NSPLIT + sp) * 64 + d] = zacc;
}

__global__ void zred_kernel(const float* __restrict__ zp, float* __restrict__ Z)
{
    int bh = blockIdx.x, d = threadIdx.x;
    float s = 0.f;
#pragma unroll
    for (int i = 0; i < NSPLIT; i++) s += zp[(bh * NSPLIT + i) * 64 + d];
    Z[bh * 64 + d] = s;
}

__global__ __launch_bounds__(256) void ctx_reduce_kernel(
    const float* __restrict__ ctxp, const float* __restrict__ Z,
    float* __restrict__ ctx)
{
    int idx = blockIdx.x * 256 + threadIdx.x;
    int bh = idx >> 12, de = idx & 4095, d = de >> 6;
    float s = 0.f;
#pragma unroll
    for (int i = 0; i < NSPLIT; i++)
        s += ctxp[((size_t)bh * NSPLIT + i) * 4096 + de];
    ctx[idx] = s / Z[bh * 64 + d];
}

// ============================================================
// W2[b][h*64+d][n] = sum_e ctx[bh][d][e] * Wlin[h*64+e][n]
// ============================================================
__global__ __launch_bounds__(256) void w2_kernel(
    const float* __restrict__ ctx, const float* __restrict__ Wlin,
    float* __restrict__ W2)
{
    int bh = blockIdx.x, nb = blockIdx.y;
    int b = bh >> 4, h = bh & 15;
    __shared__ float Cs[64][64];
    __shared__ float Ws[64][64];
    int tid = threadIdx.x;
    for (int i = tid; i < 4096; i += 256)
        ((float*)Cs)[i] = ctx[(size_t)bh * 4096 + i];
    {
        int e = tid >> 2, nq = (tid & 3) << 4;
        const float* src = Wlin + (size_t)(h * 64 + e) * 1024 + nb * 64 + nq;
#pragma unroll
        for (int j = 0; j < 4; j++)
            *(float4*)&Ws[e][nq + j * 4] = *(const float4*)(src + j * 4);
    }
    __syncthreads();
    int tr = tid >> 4, tc = tid & 15;
    float acc[4][4] = {};
#pragma unroll 8
    for (int e = 0; e < 64; e++) {
        float a0 = Cs[tr*4+0][e], a1 = Cs[tr*4+1][e];
        float a2 = Cs[tr*4+2][e], a3 = Cs[tr*4+3][e];
        float4 rb = *(const float4*)&Ws[e][tc * 4];
        acc[0][0]+=a0*rb.x; acc[0][1]+=a0*rb.y; acc[0][2]+=a0*rb.z; acc[0][3]+=a0*rb.w;
        acc[1][0]+=a1*rb.x; acc[1][1]+=a1*rb.y; acc[1][2]+=a1*rb.z; acc[1][3]+=a1*rb.w;
        acc[2][0]+=a2*rb.x; acc[2][1]+=a2*rb.y; acc[2][2]+=a2*rb.z; acc[2][3]+=a2*rb.w;
        acc[3][0]+=a3*rb.x; acc[3][1]+=a3*rb.y; acc[3][2]+=a3*rb.z; acc[3][3]+=a3*rb.w;
    }
#pragma unroll
    for (int i = 0; i < 4; i++) {
        float4 o = make_float4(acc[i][0], acc[i][1], acc[i][2], acc[i][3]);
        *(float4*)(W2 + ((size_t)b * 1024 + h * 64 + tr * 4 + i) * 1024 + nb * 64 + tc * 4) = o;
    }
}

// ============================================================
extern "C" void kernel_launch(void* const* d_in, const int* in_sizes, int n_in,
                              void* d_out, int out_size)
{
    (void)in_sizes; (void)n_in; (void)out_size;
    const float* x    = (const float*)d_in[0];
    const float* Wq   = (const float*)d_in[1];
    const float* Wkv  = (const float*)d_in[2];
    const float* Wlin = (const float*)d_in[3];
    const float* blin = (const float*)d_in[4];
    float* out = (float*)d_out;

    cudaFuncSetAttribute(gemm_mma<0>, cudaFuncAttributeMaxDynamicSharedMemorySize, SMEM_GEMM);
    cudaFuncSetAttribute(gemm_mma<1>, cudaFuncAttributeMaxDynamicSharedMemorySize, SMEM_GEMM);
    cudaFuncSetAttribute(gemm_mma<2>, cudaFuncAttributeMaxDynamicSharedMemorySize, SMEM_GEMM);

    __half *pxh, *pWqh, *pWql, *pWkh, *pWkl, *pEQ, *pYkv, *pQ, *pW2h, *pW2l;
    float *pzp, *pZ, *pctxp, *pctx, *pW2;
    cudaGetSymbolAddress((void**)&pxh,  g_xh);
    cudaGetSymbolAddress((void**)&pWqh, g_Wqt_h); cudaGetSymbolAddress((void**)&pWql, g_Wqt_l);
    cudaGetSymbolAddress((void**)&pWkh, g_Wkvt_h); cudaGetSymbolAddress((void**)&pWkl, g_Wkvt_l);
    cudaGetSymbolAddress((void**)&pEQ,  g_EQ);   cudaGetSymbolAddress((void**)&pYkv, g_Ykv);
    cudaGetSymbolAddress((void**)&pQ,   g_Q);
    cudaGetSymbolAddress((void**)&pzp,  g_zp);   cudaGetSymbolAddress((void**)&pZ,   g_Z);
    cudaGetSymbolAddress((void**)&pctxp,g_ctxp); cudaGetSymbolAddress((void**)&pctx, g_ctx);
    cudaGetSymbolAddress((void**)&pW2,  g_W2);
    cudaGetSymbolAddress((void**)&pW2h, g_W2t_h); cudaGetSymbolAddress((void**)&pW2l, g_W2t_l);

    dim3 blk(256);

    // 1) conversions
    x_to_h<<<(M_*D_/4)/256, blk>>>((const float4*)x, pxh, (size_t)M_*D_/4);
    transW_split<<<dim3(32, 32, 1), blk>>>(Wq,  pWqh, pWql, D_, D_);
    transW_split<<<dim3(64, 32, 1), blk>>>(Wkv, pWkh, pWkl, D_, 2*D_);

    // 2) projections; exp fused in epilogue (MUFU overlaps tensor)
    gemm_mma<1><<<dim3(D_/128, M_/128, 1), blk, SMEM_GEMM>>>(
        (const uint4*)pxh, (const uint4*)pWqh, (const uint4*)pWql,
        pEQ, M_, D_, D_, 0, 0, 0, nullptr);
    gemm_mma<2><<<dim3(2*D_/128, M_/128, 1), blk, SMEM_GEMM>>>(
        (const uint4*)pxh, (const uint4*)pWkh, (const uint4*)pWkl,
        pYkv, M_, 2*D_, D_, 0, 0, 0, nullptr);

    // 3) Q normalize (sum-only, no MUFU)
    qnorm<<<(M_*H_)/8, blk>>>((const __half2*)pEQ, (__half2*)pQ);

    // 4) ctx (E precomputed; pure FMA)
    ctx_partial_kernel<<<dim3(B_*H_, NSPLIT), blk>>>((const __half2*)pYkv, pctxp, pzp);
    zred_kernel<<<B_*H_, 64>>>(pzp, pZ);
    ctx_reduce_kernel<<<(B_*H_*64*64)/256, blk>>>(pctxp, pZ, pctx);

    // 5) W2 = ctx @ Wlin (per head), then transpose+split
    w2_kernel<<<dim3(B_*H_, 16), blk>>>(pctx, Wlin, pW2);
    transW_split<<<dim3(32, 32, B_), blk>>>(pW2, pW2h, pW2l, D_, D_);

    // 6) out[b] = Q[b] @ W2[b] + blin
    gemm_mma<0><<<dim3(D_/128, S_/128, B_), blk, SMEM_GEMM>>>(
        (const uint4*)pQ, (const uint4*)pW2h, (const uint4*)pW2l,
        out, S_, D_, D_,
        (size_t)S_*D_/8, (size_t)D_*D_/8, (size_t)S_*D_,
        blin);
}

// round 8
// speedup vs baseline: 1.7850x; 1.7850x over previous
#include <cuda_runtime.h>
#include <cuda_fp16.h>
#include <cstdint>

#define B_  4
#define S_  8192
#define D_  1024
#define H_  16
#define M_  (B_*S_)          // 32768
#define SCALE_ 0.125f
#define NSPLIT 16
#define SCHUNK (S_/NSPLIT)   // 512
#define NPART  (NSPLIT*4)    // 64 ctx partials per bh

// ---------------- scratch (device globals) ----------------
__device__ __half g_xh [(size_t)M_*D_];                    // x as fp16
__device__ __half g_Wqt [(size_t)D_*D_];
__device__ __half g_Wkvt[(size_t)2*D_*D_];
__device__ __half g_EQ [(size_t)M_*D_];                    // exp(Q logits)
__device__ __half g_Ykv[(size_t)M_*2*D_];                  // E=exp(K) | V (fp16)
__device__ __half g_Q  [(size_t)M_*D_];                    // normalized Q (fp16)
__device__ float g_zp[B_*H_*NPART*64];
__device__ float g_Z [B_*H_*64];
__device__ float g_ctxp[(size_t)B_*H_*NPART*64*64];        // 67 MB
__device__ float g_ctx [B_*H_*64*64];
__device__ float g_W2[(size_t)B_*D_*D_];
__device__ __half g_W2t[(size_t)B_*D_*D_];

// ---------------- helpers ----------------
__device__ __forceinline__ uint32_t smem_u32(const void* p) {
    uint32_t a;
    asm("{ .reg .u64 t; cvta.to.shared.u64 t, %1; cvt.u32.u64 %0, t; }" : "=r"(a) : "l"(p));
    return a;
}
#define SWZ(off) ((off) ^ (((off) >> 3) & 0x70))

__device__ __forceinline__ void cpa16(uint32_t s, const void* g) {
    asm volatile("cp.async.cg.shared.global [%0], [%1], 16;" :: "r"(s), "l"(g));
}
#define CP_COMMIT() asm volatile("cp.async.commit_group;" ::: "memory")
#define CP_WAITG(n) asm volatile("cp.async.wait_group %0;" :: "n"(n) : "memory")

#define LDSM4(r, addr)                                                        \
    asm volatile("ldmatrix.sync.aligned.m8n8.x4.shared.b16 {%0,%1,%2,%3}, [%4];" \
        : "=r"((r)[0]), "=r"((r)[1]), "=r"((r)[2]), "=r"((r)[3]) : "r"(addr))

#define MMA16816(c, a, b0, b1)                                                \
    asm volatile("mma.sync.aligned.m16n8k16.row.col.f32.f16.f16.f32 "         \
        "{%0,%1,%2,%3},{%4,%5,%6,%7},{%8,%9},{%0,%1,%2,%3};"                  \
        : "+f"((c)[0]), "+f"((c)[1]), "+f"((c)[2]), "+f"((c)[3])              \
        : "r"((a)[0]), "r"((a)[1]), "r"((a)[2]), "r"((a)[3]),                 \
          "r"(b0), "r"(b1))

static constexpr int STAGE = 32768;           // A16K B16K
static constexpr int SMEM_GEMM = 3 * STAGE;   // 96KB, 3-stage -> 2 CTAs/SM

// EPI modes: 0 = fp32 out + bias, 1 = fp16 exp(acc) all cols,
//            2 = fp16, exp(acc) only on K-columns ((n>>6)&1 == 0)
// ============================================================
// HMMA GEMM: C[M,N] = A[M,K] @ B[N,K]^T  (all fp16 operands)
// CTA 128x128xK64, 8 warps (64x32), 3-stage cp.async, SW128 smem.
// ============================================================
template<int EPI>
__global__ __launch_bounds__(256, 2) void gemm_mma(
    const uint4* __restrict__ A, const uint4* __restrict__ Bm,
    void* __restrict__ Cv, int M, int N, int K,
    size_t aBatch, size_t bBatch, size_t cBatch,
    const float* __restrict__ bias)
{
    extern __shared__ __align__(1024) char smem[];
    const uint32_t sbase = smem_u32(smem);
    const int tid = threadIdx.x, wid = tid >> 5, lane = tid & 31;
    const int bn = blockIdx.x * 128, bm = blockIdx.y * 128;
    const int z = blockIdx.z;
    A  += (size_t)z * aBatch;
    Bm += (size_t)z * bBatch;

    const int wm = (wid >> 2) * 64;
    const int wn = (wid & 3) * 32;
    const int Kq = K >> 3;

    const int lr = lane & 7, lq = lane >> 3;
    const uint32_t aRow = lr + (lq & 1) * 8,  aColB = (lq >> 1) * 16;
    const uint32_t bRow = lr + (lq >> 1) * 8, bColB = (lq & 1) * 16;

    float acc[4][4][4] = {};

    auto load_stage = [&](int s, int kq0) {
        uint32_t stb = sbase + s * STAGE;
#pragma unroll
        for (int ii = 0; ii < 4; ii++) {
            int i = tid + ii * 256;
            int r = i >> 3, cc = i & 7;
            uint32_t off = SWZ((uint32_t)(r * 128 + cc * 16));
            cpa16(stb + off,          A  + (size_t)(bm + r) * Kq + kq0 + cc);
            cpa16(stb + 16384 + off,  Bm + (size_t)(bn + r) * Kq + kq0 + cc);
        }
    };

    const int nch = K >> 6;
    load_stage(0, 0);  CP_COMMIT();
    load_stage(1, 8);  CP_COMMIT();

    for (int c = 0; c < nch; ++c) {
        if (c + 1 < nch) { CP_WAITG(1); } else { CP_WAITG(0); }
        __syncthreads();
        if (c + 2 < nch) { load_stage((c + 2) % 3, (c + 2) * 8); CP_COMMIT(); }

        const uint32_t stb = sbase + (c % 3) * STAGE;
#pragma unroll
        for (int t = 0; t < 4; t++) {
            uint32_t a4[4][4], b4[2][4];
#pragma unroll
            for (int mf = 0; mf < 4; mf++) {
                uint32_t off = SWZ((uint32_t)((wm + mf * 16 + aRow) * 128 + t * 32 + aColB));
                LDSM4(a4[mf], stb + off);
            }
#pragma unroll
            for (int p = 0; p < 2; p++) {
                uint32_t off = SWZ((uint32_t)((wn + p * 16 + bRow) * 128 + t * 32 + bColB));
                LDSM4(b4[p], stb + 16384 + off);
            }
#pragma unroll
            for (int mf = 0; mf < 4; mf++)
#pragma unroll
                for (int nf = 0; nf < 4; nf++) {
                    int p = nf >> 1, hh = (nf & 1) * 2;
                    MMA16816(acc[mf][nf], a4[mf], b4[p][hh], b4[p][hh + 1]);
                }
        }
    }

    // epilogue
    const int g = lane >> 2, tt = lane & 3;
#pragma unroll
    for (int mf = 0; mf < 4; mf++)
#pragma unroll
        for (int nf = 0; nf < 4; nf++) {
            int m = bm + wm + mf * 16 + g;
            int n = bn + wn + nf * 8 + tt * 2;
            float v0 = acc[mf][nf][0], v1 = acc[mf][nf][1];
            float v2 = acc[mf][nf][2], v3 = acc[mf][nf][3];
            if constexpr (EPI == 0) {
                float b0 = bias[n], b1 = bias[n + 1];
                float* C = (float*)Cv + (size_t)z * cBatch;
                *(float2*)(C + (size_t)m * N + n)       = make_float2(v0 + b0, v1 + b1);
                *(float2*)(C + (size_t)(m + 8) * N + n) = make_float2(v2 + b0, v3 + b1);
            } else {
                bool doexp = (EPI == 1) || (((n >> 6) & 1) == 0);
                if (doexp) {
                    v0 = __expf(v0); v1 = __expf(v1);
                    v2 = __expf(v2); v3 = __expf(v3);
                }
                __half* C = (__half*)Cv + (size_t)z * cBatch;
                *(__half2*)(C + (size_t)m * N + n)       = __floats2half2_rn(v0, v1);
                *(__half2*)(C + (size_t)(m + 8) * N + n) = __floats2half2_rn(v2, v3);
            }
        }
}

// ============================================================
// x fp32 -> fp16 (elementwise)
// ============================================================
__global__ __launch_bounds__(256) void x_to_h(
    const float4* __restrict__ X, __half* __restrict__ O, size_t n4)
{
    size_t i = (size_t)blockIdx.x * 256 + threadIdx.x;
    if (i >= n4) return;
    float4 v = X[i];
    __half2* p = (__half2*)(O + i * 4);
    p[0] = __floats2half2_rn(v.x, v.y);
    p[1] = __floats2half2_rn(v.z, v.w);
}

// ============================================================
// W[K,N] -> transposed fp16 [N,K]  (batched via z)
// ============================================================
__global__ __launch_bounds__(256) void transW_h(
    const float* __restrict__ W, __half* __restrict__ Th, int K, int N)
{
    __shared__ float t[32][33];
    const size_t zoff = (size_t)blockIdx.z * K * N;
    W += zoff; Th += zoff;
    int n0 = blockIdx.x * 32, k0 = blockIdx.y * 32;
    int tx = threadIdx.x & 31, ty = threadIdx.x >> 5;
#pragma unroll
    for (int i = 0; i < 32; i += 8)
        t[ty + i][tx] = W[(size_t)(k0 + ty + i) * N + n0 + tx];
    __syncthreads();
#pragma unroll
    for (int i = 0; i < 32; i += 8)
        Th[(size_t)(n0 + ty + i) * K + k0 + tx] = __float2half_rn(t[tx][ty + i]);
}

// ============================================================
// Q normalize: Q[w,:] = EQ[w,:] * SCALE / sum(EQ[w,:])
// ============================================================
__global__ __launch_bounds__(256) void qnorm(
    const __half2* __restrict__ EQ, __half2* __restrict__ Q)
{
    int w = (blockIdx.x * blockDim.x + threadIdx.x) >> 5;
    int lane = threadIdx.x & 31;
    float2 f = __half22float2(EQ[(size_t)w * 32 + lane]);
    float s = f.x + f.y;
#pragma unroll
    for (int o = 16; o; o >>= 1) s += __shfl_xor_sync(0xffffffffu, s, o);
    float inv = SCALE_ / s;
    Q[(size_t)w * 32 + lane] = __floats2half2_rn(f.x * inv, f.y * inv);
}

// ============================================================
// ctx partials, high arithmetic intensity:
// thread = (dg, eg, sspar): owns 4d x 16e accumulator, s-stride 4.
// ctxp[bh][sp*4+sspar][d][e] = sum_{s in slice} E[s,d] * V[s,e]
// ============================================================
__global__ __launch_bounds__(256) void ctx_partial_kernel(
    const __half2* __restrict__ Ykv2, float* __restrict__ ctxp,
    float* __restrict__ zp)
{
    int bh = blockIdx.x, sp = blockIdx.y;
    int b = bh >> 4, h = bh & 15;
    int tid = threadIdx.x;
    int dg = tid >> 4;            // 0..15 -> d = dg*4
    int eg = (tid >> 2) & 3;      // 0..3  -> e = eg*16
    int sspar = tid & 3;          // 0..3
    __shared__ float Ek[8][64];
    __shared__ float Vt[8][68];   // pad to dodge conflicts
    float acc[4][16] = {};
    float zacc[4] = {0.f, 0.f, 0.f, 0.f};
    const __half2* base = Ykv2 + (size_t)(b * S_ + sp * SCHUNK) * 1024 + h * 64;
    for (int s0 = 0; s0 < SCHUNK; s0 += 8) {
#pragma unroll
        for (int i = 0; i < 2; i++) {
            int idx = tid + i * 256;
            int ss = idx >> 6, c2 = idx & 63;
            float2 f = __half22float2(base[(size_t)(s0 + ss) * 1024 + c2]);
            if (c2 < 32) { Ek[ss][2*c2] = f.x;    Ek[ss][2*c2+1] = f.y; }
            else         { Vt[ss][2*c2-64] = f.x; Vt[ss][2*c2-63] = f.y; }
        }
        __syncthreads();
#pragma unroll
        for (int sj = 0; sj < 2; sj++) {
            int ss = sspar + sj * 4;
            float4 ev = *(const float4*)&Ek[ss][dg * 4];
            float v[16];
#pragma unroll
            for (int j = 0; j < 4; j++)
                *(float4*)&v[j*4] = *(const float4*)&Vt[ss][eg * 16 + j * 4];
            const float ed[4] = {ev.x, ev.y, ev.z, ev.w};
#pragma unroll
            for (int dd = 0; dd < 4; dd++) {
                if (eg == 0) zacc[dd] += ed[dd] * 0.25f;  // each d summed by 4 sspar? no:
#pragma unroll
                for (int j = 0; j < 16; j++)
                    acc[dd][j] += ed[dd] * v[j];
            }
        }
        __syncthreads();
    }
    // NOTE: zacc guard — each (dg, sspar) with eg==0 accumulates its own s-slice,
    // partials are distinct per sspar, so no over-count: undo the 0.25 factor? see below.
    size_t po = (((size_t)bh * NSPLIT + sp) * 4 + sspar) * 4096;
#pragma unroll
    for (int dd = 0; dd < 4; dd++) {
        float* o = ctxp + po + (dg * 4 + dd) * 64 + eg * 16;
#pragma unroll
        for (int j = 0; j < 4; j++)
            *(float4*)(o + j * 4) = make_float4(acc[dd][j*4], acc[dd][j*4+1],
                                                acc[dd][j*4+2], acc[dd][j*4+3]);
        if (eg == 0)
            zp[(((size_t)bh * NSPLIT + sp) * 4 + sspar) * 64 + dg * 4 + dd] = zacc[dd] * 4.0f;
    }
}

__global__ void zred_kernel(const float* __restrict__ zp, float* __restrict__ Z)
{
    int bh = blockIdx.x, d = threadIdx.x;
    float s = 0.f;
#pragma unroll
    for (int i = 0; i < NPART; i++) s += zp[((size_t)bh * NPART + i) * 64 + d];
    Z[bh * 64 + d] = s;
}

__global__ __launch_bounds__(256) void ctx_reduce_kernel(
    const float* __restrict__ ctxp, const float* __restrict__ Z,
    float* __restrict__ ctx)
{
    int idx = blockIdx.x * 256 + threadIdx.x;
    int bh = idx >> 12, de = idx & 4095, d = de >> 6;
    float s = 0.f;
#pragma unroll
    for (int i = 0; i < NPART; i++)
        s += ctxp[((size_t)bh * NPART + i) * 4096 + de];
    ctx[idx] = s / Z[bh * 64 + d];
}

// ============================================================
// W2[b][h*64+d][n] = sum_e ctx[bh][d][e] * Wlin[h*64+e][n]
// ============================================================
__global__ __launch_bounds__(256) void w2_kernel(
    const float* __restrict__ ctx, const float* __restrict__ Wlin,
    float* __restrict__ W2)
{
    int bh = blockIdx.x, nb = blockIdx.y;
    int b = bh >> 4, h = bh & 15;
    __shared__ float Cs[64][64];
    __shared__ float Ws[64][64];
    int tid = threadIdx.x;
    for (int i = tid; i < 4096; i += 256)
        ((float*)Cs)[i] = ctx[(size_t)bh * 4096 + i];
    {
        int e = tid >> 2, nq = (tid & 3) << 4;
        const float* src = Wlin + (size_t)(h * 64 + e) * 1024 + nb * 64 + nq;
#pragma unroll
        for (int j = 0; j < 4; j++)
            *(float4*)&Ws[e][nq + j * 4] = *(const float4*)(src + j * 4);
    }
    __syncthreads();
    int tr = tid >> 4, tc = tid & 15;
    float acc[4][4] = {};
#pragma unroll 8
    for (int e = 0; e < 64; e++) {
        float a0 = Cs[tr*4+0][e], a1 = Cs[tr*4+1][e];
        float a2 = Cs[tr*4+2][e], a3 = Cs[tr*4+3][e];
        float4 rb = *(const float4*)&Ws[e][tc * 4];
        acc[0][0]+=a0*rb.x; acc[0][1]+=a0*rb.y; acc[0][2]+=a0*rb.z; acc[0][3]+=a0*rb.w;
        acc[1][0]+=a1*rb.x; acc[1][1]+=a1*rb.y; acc[1][2]+=a1*rb.z; acc[1][3]+=a1*rb.w;
        acc[2][0]+=a2*rb.x; acc[2][1]+=a2*rb.y; acc[2][2]+=a2*rb.z; acc[2][3]+=a2*rb.w;
        acc[3][0]+=a3*rb.x; acc[3][1]+=a3*rb.y; acc[3][2]+=a3*rb.z; acc[3][3]+=a3*rb.w;
    }
#pragma unroll
    for (int i = 0; i < 4; i++) {
        float4 o = make_float4(acc[i][0], acc[i][1], acc[i][2], acc[i][3]);
        *(float4*)(W2 + ((size_t)b * 1024 + h * 64 + tr * 4 + i) * 1024 + nb * 64 + tc * 4) = o;
    }
}

// ============================================================
extern "C" void kernel_launch(void* const* d_in, const int* in_sizes, int n_in,
                              void* d_out, int out_size)
{
    (void)in_sizes; (void)n_in; (void)out_size;
    const float* x    = (const float*)d_in[0];
    const float* Wq   = (const float*)d_in[1];
    const float* Wkv  = (const float*)d_in[2];
    const float* Wlin = (const float*)d_in[3];
    const float* blin = (const float*)d_in[4];
    float* out = (float*)d_out;

    cudaFuncSetAttribute(gemm_mma<0>, cudaFuncAttributeMaxDynamicSharedMemorySize, SMEM_GEMM);
    cudaFuncSetAttribute(gemm_mma<1>, cudaFuncAttributeMaxDynamicSharedMemorySize, SMEM_GEMM);
    cudaFuncSetAttribute(gemm_mma<2>, cudaFuncAttributeMaxDynamicSharedMemorySize, SMEM_GEMM);

    __half *pxh, *pWq, *pWkv, *pEQ, *pYkv, *pQ, *pW2t;
    float *pzp, *pZ, *pctxp, *pctx, *pW2;
    cudaGetSymbolAddress((void**)&pxh,  g_xh);
    cudaGetSymbolAddress((void**)&pWq,  g_Wqt);
    cudaGetSymbolAddress((void**)&pWkv, g_Wkvt);
    cudaGetSymbolAddress((void**)&pEQ,  g_EQ);   cudaGetSymbolAddress((void**)&pYkv, g_Ykv);
    cudaGetSymbolAddress((void**)&pQ,   g_Q);
    cudaGetSymbolAddress((void**)&pzp,  g_zp);   cudaGetSymbolAddress((void**)&pZ,   g_Z);
    cudaGetSymbolAddress((void**)&pctxp,g_ctxp); cudaGetSymbolAddress((void**)&pctx, g_ctx);
    cudaGetSymbolAddress((void**)&pW2,  g_W2);   cudaGetSymbolAddress((void**)&pW2t, g_W2t);

    dim3 blk(256);

    // 1) conversions
    x_to_h<<<(M_*D_/4)/256, blk>>>((const float4*)x, pxh, (size_t)M_*D_/4);
    transW_h<<<dim3(32, 32, 1), blk>>>(Wq,  pWq,  D_, D_);
    transW_h<<<dim3(64, 32, 1), blk>>>(Wkv, pWkv, D_, 2*D_);

    // 2) projections; exp fused in epilogue
    gemm_mma<1><<<dim3(D_/128, M_/128, 1), blk, SMEM_GEMM>>>(
        (const uint4*)pxh, (const uint4*)pWq,
        pEQ, M_, D_, D_, 0, 0, 0, nullptr);
    gemm_mma<2><<<dim3(2*D_/128, M_/128, 1), blk, SMEM_GEMM>>>(
        (const uint4*)pxh, (const uint4*)pWkv,
        pYkv, M_, 2*D_, D_, 0, 0, 0, nullptr);

    // 3) Q normalize
    qnorm<<<(M_*H_)/8, blk>>>((const __half2*)pEQ, (__half2*)pQ);

    // 4) ctx
    ctx_partial_kernel<<<dim3(B_*H_, NSPLIT), blk>>>((const __half2*)pYkv, pctxp, pzp);
    zred_kernel<<<B_*H_, 64>>>(pzp, pZ);
    ctx_reduce_kernel<<<(B_*H_*64*64)/256, blk>>>(pctxp, pZ, pctx);

    // 5) W2 = ctx @ Wlin (per head), then transpose
    w2_kernel<<<dim3(B_*H_, 16), blk>>>(pctx, Wlin, pW2);
    transW_h<<<dim3(32, 32, B_), blk>>>(pW2, pW2t, D_, D_);

    // 6) out[b] = Q[b] @ W2[b] + blin
    gemm_mma<0><<<dim3(D_/128, S_/128, B_), blk, SMEM_GEMM>>>(
        (const uint4*)pQ, (const uint4*)pW2t,
        out, S_, D_, D_,
        (size_t)S_*D_/8, (size_t)D_*D_/8, (size_t)S_*D_,
        blin);
}

// round 9
// speedup vs baseline: 2.3282x; 1.3043x over previous
#include <cuda_runtime.h>
#include <cuda_fp16.h>
#include <cstdint>

#define B_  4
#define S_  8192
#define D_  1024
#define H_  16
#define M_  (B_*S_)          // 32768
#define SCALE_ 0.125f
#define NSPLIT 16
#define SCHUNK (S_/NSPLIT)   // 512

// ---------------- scratch (device globals) ----------------
__device__ __half g_xh [(size_t)M_*D_];                    // x as fp16
__device__ __half g_Wqt [(size_t)D_*D_];
__device__ __half g_Wkvt[(size_t)2*D_*D_];
__device__ __half g_EQ [(size_t)M_*D_];                    // exp(Q logits)
__device__ __half g_Ykv[(size_t)M_*2*D_];                  // E=exp(K) | V (fp16)
__device__ __half g_Q  [(size_t)M_*D_];                    // normalized Q (fp16)
__device__ float g_zp[B_*H_*NSPLIT*64];
__device__ float g_Z [B_*H_*64];
__device__ float g_ctxp[(size_t)B_*H_*NSPLIT*64*64];       // 16.8 MB
__device__ float g_ctx [B_*H_*64*64];
__device__ float g_W2[(size_t)B_*D_*D_];
__device__ __half g_W2t[(size_t)B_*D_*D_];

// ---------------- helpers ----------------
__device__ __forceinline__ uint32_t smem_u32(const void* p) {
    uint32_t a;
    asm("{ .reg .u64 t; cvta.to.shared.u64 t, %1; cvt.u32.u64 %0, t; }" : "=r"(a) : "l"(p));
    return a;
}
#define SWZ(off) ((off) ^ (((off) >> 3) & 0x70))

__device__ __forceinline__ void cpa16(uint32_t s, const void* g) {
    asm volatile("cp.async.cg.shared.global [%0], [%1], 16;" :: "r"(s), "l"(g));
}
#define CP_COMMIT() asm volatile("cp.async.commit_group;" ::: "memory")
#define CP_WAITG(n) asm volatile("cp.async.wait_group %0;" :: "n"(n) : "memory")

#define LDSM4(r, addr)                                                        \
    asm volatile("ldmatrix.sync.aligned.m8n8.x4.shared.b16 {%0,%1,%2,%3}, [%4];" \
        : "=r"((r)[0]), "=r"((r)[1]), "=r"((r)[2]), "=r"((r)[3]) : "r"(addr))

#define LDSM4T(r, addr)                                                       \
    asm volatile("ldmatrix.sync.aligned.m8n8.x4.trans.shared.b16 {%0,%1,%2,%3}, [%4];" \
        : "=r"((r)[0]), "=r"((r)[1]), "=r"((r)[2]), "=r"((r)[3]) : "r"(addr))

#define MMA16816(c, a, b0, b1)                                                \
    asm volatile("mma.sync.aligned.m16n8k16.row.col.f32.f16.f16.f32 "         \
        "{%0,%1,%2,%3},{%4,%5,%6,%7},{%8,%9},{%0,%1,%2,%3};"                  \
        : "+f"((c)[0]), "+f"((c)[1]), "+f"((c)[2]), "+f"((c)[3])              \
        : "r"((a)[0]), "r"((a)[1]), "r"((a)[2]), "r"((a)[3]),                 \
          "r"(b0), "r"(b1))

static constexpr int STAGE = 32768;           // A16K B16K
static constexpr int SMEM_GEMM = 3 * STAGE;   // 96KB, 3-stage -> 2 CTAs/SM

// EPI modes: 0 = fp32 out + bias, 1 = fp16 exp(acc) all cols,
//            2 = fp16, exp(acc) only on K-columns ((n>>6)&1 == 0)
// ============================================================
// HMMA GEMM: C[M,N] = A[M,K] @ B[N,K]^T  (all fp16 operands)
// CTA 128x128xK64, 8 warps (64x32), 3-stage cp.async, SW128 smem.
// ============================================================
template<int EPI>
__global__ __launch_bounds__(256, 2) void gemm_mma(
    const uint4* __restrict__ A, const uint4* __restrict__ Bm,
    void* __restrict__ Cv, int M, int N, int K,
    size_t aBatch, size_t bBatch, size_t cBatch,
    const float* __restrict__ bias)
{
    extern __shared__ __align__(1024) char smem[];
    const uint32_t sbase = smem_u32(smem);
    const int tid = threadIdx.x, wid = tid >> 5, lane = tid & 31;
    const int bn = blockIdx.x * 128, bm = blockIdx.y * 128;
    const int z = blockIdx.z;
    A  += (size_t)z * aBatch;
    Bm += (size_t)z * bBatch;

    const int wm = (wid >> 2) * 64;
    const int wn = (wid & 3) * 32;
    const int Kq = K >> 3;

    const int lr = lane & 7, lq = lane >> 3;
    const uint32_t aRow = lr + (lq & 1) * 8,  aColB = (lq >> 1) * 16;
    const uint32_t bRow = lr + (lq >> 1) * 8, bColB = (lq & 1) * 16;

    float acc[4][4][4] = {};

    auto load_stage = [&](int s, int kq0) {
        uint32_t stb = sbase + s * STAGE;
#pragma unroll
        for (int ii = 0; ii < 4; ii++) {
            int i = tid + ii * 256;
            int r = i >> 3, cc = i & 7;
            uint32_t off = SWZ((uint32_t)(r * 128 + cc * 16));
            cpa16(stb + off,          A  + (size_t)(bm + r) * Kq + kq0 + cc);
            cpa16(stb + 16384 + off,  Bm + (size_t)(bn + r) * Kq + kq0 + cc);
        }
    };

    const int nch = K >> 6;
    load_stage(0, 0);  CP_COMMIT();
    load_stage(1, 8);  CP_COMMIT();

    for (int c = 0; c < nch; ++c) {
        if (c + 1 < nch) { CP_WAITG(1); } else { CP_WAITG(0); }
        __syncthreads();
        if (c + 2 < nch) { load_stage((c + 2) % 3, (c + 2) * 8); CP_COMMIT(); }

        const uint32_t stb = sbase + (c % 3) * STAGE;
#pragma unroll
        for (int t = 0; t < 4; t++) {
            uint32_t a4[4][4], b4[2][4];
#pragma unroll
            for (int mf = 0; mf < 4; mf++) {
                uint32_t off = SWZ((uint32_t)((wm + mf * 16 + aRow) * 128 + t * 32 + aColB));
                LDSM4(a4[mf], stb + off);
            }
#pragma unroll
            for (int p = 0; p < 2; p++) {
                uint32_t off = SWZ((uint32_t)((wn + p * 16 + bRow) * 128 + t * 32 + bColB));
                LDSM4(b4[p], stb + 16384 + off);
            }
#pragma unroll
            for (int mf = 0; mf < 4; mf++)
#pragma unroll
                for (int nf = 0; nf < 4; nf++) {
                    int p = nf >> 1, hh = (nf & 1) * 2;
                    MMA16816(acc[mf][nf], a4[mf], b4[p][hh], b4[p][hh + 1]);
                }
        }
    }

    // epilogue
    const int g = lane >> 2, tt = lane & 3;
#pragma unroll
    for (int mf = 0; mf < 4; mf++)
#pragma unroll
        for (int nf = 0; nf < 4; nf++) {
            int m = bm + wm + mf * 16 + g;
            int n = bn + wn + nf * 8 + tt * 2;
            float v0 = acc[mf][nf][0], v1 = acc[mf][nf][1];
            float v2 = acc[mf][nf][2], v3 = acc[mf][nf][3];
            if constexpr (EPI == 0) {
                float b0 = bias[n], b1 = bias[n + 1];
                float* C = (float*)Cv + (size_t)z * cBatch;
                *(float2*)(C + (size_t)m * N + n)       = make_float2(v0 + b0, v1 + b1);
                *(float2*)(C + (size_t)(m + 8) * N + n) = make_float2(v2 + b0, v3 + b1);
            } else {
                bool doexp = (EPI == 1) || (((n >> 6) & 1) == 0);
                if (doexp) {
                    v0 = __expf(v0); v1 = __expf(v1);
                    v2 = __expf(v2); v3 = __expf(v3);
                }
                __half* C = (__half*)Cv + (size_t)z * cBatch;
                *(__half2*)(C + (size_t)m * N + n)       = __floats2half2_rn(v0, v1);
                *(__half2*)(C + (size_t)(m + 8) * N + n) = __floats2half2_rn(v2, v3);
            }
        }
}

// ============================================================
// ctx via tensor cores:
// ctxp[bh][sp][d][e] = sum_{s in chunk} E[s,d] * V[s,e]
// A[m=d,k=s] = E^T  (ldsm.x4.trans on E[s,d] tiles)
// B[n=e,k=s] = V^T  (ldsm.x4.trans on V[s,e] tiles)
// CTA: 128 thr (4 warps, 32d x 32e each), dbuf 64-s blocks.
// ============================================================
static constexpr int CTX_STAGE = 16384;       // E 8KB + V 8KB
__global__ __launch_bounds__(128) void ctx_mma(
    const __half* __restrict__ Ykv, float* __restrict__ ctxp)
{
    __shared__ __align__(1024) char smem[2 * CTX_STAGE];
    const uint32_t sb = smem_u32(smem);
    const int bh = blockIdx.x, sp = blockIdx.y;
    const int b = bh >> 4, h = bh & 15;
    const int tid = threadIdx.x, wid = tid >> 5, lane = tid & 31;
    const __half* base = Ykv + ((size_t)(b * S_) + sp * SCHUNK) * 2048 + h * 128;

    auto load_blk = [&](int st, int s0) {
        uint32_t stb = sb + st * CTX_STAGE;
#pragma unroll
        for (int ii = 0; ii < 8; ii++) {
            int i = tid + ii * 128;
            int r = i >> 4, q = i & 15;          // q<8: E chunk q ; q>=8: V chunk q-8
            const __half* g = base + (size_t)(s0 + r) * 2048 + (q & 7) * 8 + (q >> 3) * 64;
            uint32_t off = ((q < 8) ? 0u : 8192u) + SWZ((uint32_t)(r * 128 + (q & 7) * 16));
            cpa16(stb + off, g);
        }
    };

    const int wd = (wid & 1) * 32, we = (wid >> 1) * 32;
    const int lr = lane & 7, lg = lane >> 3;
    float acc[2][4][4] = {};

    load_blk(0, 0); CP_COMMIT();
    for (int blk = 0; blk < SCHUNK / 64; blk++) {
        if (blk + 1 < SCHUNK / 64) {
            load_blk((blk + 1) & 1, (blk + 1) * 64);
            CP_COMMIT(); CP_WAITG(1);
        } else {
            CP_WAITG(0);
        }
        __syncthreads();
        const uint32_t Es = sb + (blk & 1) * CTX_STAGE;
        const uint32_t Vs = Es + 8192;
#pragma unroll
        for (int t = 0; t < 4; t++) {            // k-steps of s16
            uint32_t a4[2][4], b4[2][4];
            // A: groups: reg0 (d0-7,s0-7)<-E rows s0-7 col d0 ; reg1 col d0+8 ;
            //            reg2 rows s8-15 col d0 ; reg3 rows s8-15 col d0+8
#pragma unroll
            for (int mi = 0; mi < 2; mi++) {
                uint32_t srow = t * 16 + lr + ((lg >> 1) & 1) * 8;
                uint32_t scolB = (wd + mi * 16) * 2 + (lg & 1) * 16;
                LDSM4T(a4[mi], Es + SWZ(srow * 128 + scolB));
            }
            // B: reg0 ntile(e0) k0-7 <- V rows s0-7 col e0 ; reg1 rows s8-15 ;
            //    reg2 ntile(e0+8) k0-7 ; reg3 ntile(e0+8) k8-15
#pragma unroll
            for (int np = 0; np < 2; np++) {
                uint32_t srow = t * 16 + lr + (lg & 1) * 8;
                uint32_t scolB = (we + np * 16) * 2 + (lg >> 1) * 16;
                LDSM4T(b4[np], Vs + SWZ(srow * 128 + scolB));
            }
#pragma unroll
            for (int mi = 0; mi < 2; mi++)
#pragma unroll
                for (int j = 0; j < 4; j++)
                    MMA16816(acc[mi][j], a4[mi], b4[j >> 1][(j & 1) * 2], b4[j >> 1][(j & 1) * 2 + 1]);
        }
        __syncthreads();
    }

    const int g = lane >> 2, tt = lane & 3;
    const size_t po = ((size_t)bh * NSPLIT + sp) * 4096;
#pragma unroll
    for (int mi = 0; mi < 2; mi++)
#pragma unroll
        for (int j = 0; j < 4; j++) {
            int d = wd + mi * 16 + g, e = we + j * 8 + tt * 2;
            *(float2*)(ctxp + po + (size_t)d * 64 + e)       = make_float2(acc[mi][j][0], acc[mi][j][1]);
            *(float2*)(ctxp + po + (size_t)(d + 8) * 64 + e) = make_float2(acc[mi][j][2], acc[mi][j][3]);
        }
}

// ============================================================
// Z partials: zp[bh][sp][d] = sum_{s in chunk} E[s,d]
// ============================================================
__global__ __launch_bounds__(256) void zsum(
    const __half* __restrict__ Ykv, float* __restrict__ zp)
{
    int bh = blockIdx.x, sp = blockIdx.y;
    int b = bh >> 4, h = bh & 15;
    int tid = threadIdx.x;
    int d = tid & 63, sy = tid >> 6;
    const __half* base = Ykv + ((size_t)(b * S_) + sp * SCHUNK) * 2048 + h * 128 + d;
    float z = 0.f;
    for (int s = sy; s < SCHUNK; s += 4) z += __half2float(base[(size_t)s * 2048]);
    __shared__ float sz[4][64];
    sz[sy][d] = z;
    __syncthreads();
    if (sy == 0)
        zp[((size_t)bh * NSPLIT + sp) * 64 + d] = sz[0][d] + sz[1][d] + sz[2][d] + sz[3][d];
}

__global__ void zred_kernel(const float* __restrict__ zp, float* __restrict__ Z)
{
    int bh = blockIdx.x, d = threadIdx.x;
    float s = 0.f;
#pragma unroll
    for (int i = 0; i < NSPLIT; i++) s += zp[((size_t)bh * NSPLIT + i) * 64 + d];
    Z[bh * 64 + d] = s;
}

__global__ __launch_bounds__(256) void ctx_reduce_kernel(
    const float* __restrict__ ctxp, const float* __restrict__ Z,
    float* __restrict__ ctx)
{
    int idx = blockIdx.x * 256 + threadIdx.x;
    int bh = idx >> 12, de = idx & 4095, d = de >> 6;
    float s = 0.f;
#pragma unroll
    for (int i = 0; i < NSPLIT; i++)
        s += ctxp[((size_t)bh * NSPLIT + i) * 4096 + de];
    ctx[idx] = s / Z[bh * 64 + d];
}

// ============================================================
// x fp32 -> fp16 (elementwise)
// ============================================================
__global__ __launch_bounds__(256) void x_to_h(
    const float4* __restrict__ X, __half* __restrict__ O, size_t n4)
{
    size_t i = (size_t)blockIdx.x * 256 + threadIdx.x;
    if (i >= n4) return;
    float4 v = X[i];
    __half2* p = (__half2*)(O + i * 4);
    p[0] = __floats2half2_rn(v.x, v.y);
    p[1] = __floats2half2_rn(v.z, v.w);
}

// ============================================================
// W[K,N] -> transposed fp16 [N,K]  (batched via z)
// ============================================================
__global__ __launch_bounds__(256) void transW_h(
    const float* __restrict__ W, __half* __restrict__ Th, int K, int N)
{
    __shared__ float t[32][33];
    const size_t zoff = (size_t)blockIdx.z * K * N;
    W += zoff; Th += zoff;
    int n0 = blockIdx.x * 32, k0 = blockIdx.y * 32;
    int tx = threadIdx.x & 31, ty = threadIdx.x >> 5;
#pragma unroll
    for (int i = 0; i < 32; i += 8)
        t[ty + i][tx] = W[(size_t)(k0 + ty + i) * N + n0 + tx];
    __syncthreads();
#pragma unroll
    for (int i = 0; i < 32; i += 8)
        Th[(size_t)(n0 + ty + i) * K + k0 + tx] = __float2half_rn(t[tx][ty + i]);
}

// ============================================================
// Q normalize: Q[w,:] = EQ[w,:] * SCALE / sum(EQ[w,:])
// ============================================================
__global__ __launch_bounds__(256) void qnorm(
    const __half2* __restrict__ EQ, __half2* __restrict__ Q)
{
    int w = (blockIdx.x * blockDim.x + threadIdx.x) >> 5;
    int lane = threadIdx.x & 31;
    float2 f = __half22float2(EQ[(size_t)w * 32 + lane]);
    float s = f.x + f.y;
#pragma unroll
    for (int o = 16; o; o >>= 1) s += __shfl_xor_sync(0xffffffffu, s, o);
    float inv = SCALE_ / s;
    Q[(size_t)w * 32 + lane] = __floats2half2_rn(f.x * inv, f.y * inv);
}

// ============================================================
// W2[b][h*64+d][n] = sum_e ctx[bh][d][e] * Wlin[h*64+e][n]
// ============================================================
__global__ __launch_bounds__(256) void w2_kernel(
    const float* __restrict__ ctx, const float* __restrict__ Wlin,
    float* __restrict__ W2)
{
    int bh = blockIdx.x, nb = blockIdx.y;
    int b = bh >> 4, h = bh & 15;
    __shared__ float Cs[64][64];
    __shared__ float Ws[64][64];
    int tid = threadIdx.x;
    for (int i = tid; i < 4096; i += 256)
        ((float*)Cs)[i] = ctx[(size_t)bh * 4096 + i];
    {
        int e = tid >> 2, nq = (tid & 3) << 4;
        const float* src = Wlin + (size_t)(h * 64 + e) * 1024 + nb * 64 + nq;
#pragma unroll
        for (int j = 0; j < 4; j++)
            *(float4*)&Ws[e][nq + j * 4] = *(const float4*)(src + j * 4);
    }
    __syncthreads();
    int tr = tid >> 4, tc = tid & 15;
    float acc[4][4] = {};
#pragma unroll 8
    for (int e = 0; e < 64; e++) {
        float a0 = Cs[tr*4+0][e], a1 = Cs[tr*4+1][e];
        float a2 = Cs[tr*4+2][e], a3 = Cs[tr*4+3][e];
        float4 rb = *(const float4*)&Ws[e][tc * 4];
        acc[0][0]+=a0*rb.x; acc[0][1]+=a0*rb.y; acc[0][2]+=a0*rb.z; acc[0][3]+=a0*rb.w;
        acc[1][0]+=a1*rb.x; acc[1][1]+=a1*rb.y; acc[1][2]+=a1*rb.z; acc[1][3]+=a1*rb.w;
        acc[2][0]+=a2*rb.x; acc[2][1]+=a2*rb.y; acc[2][2]+=a2*rb.z; acc[2][3]+=a2*rb.w;
        acc[3][0]+=a3*rb.x; acc[3][1]+=a3*rb.y; acc[3][2]+=a3*rb.z; acc[3][3]+=a3*rb.w;
    }
#pragma unroll
    for (int i = 0; i < 4; i++) {
        float4 o = make_float4(acc[i][0], acc[i][1], acc[i][2], acc[i][3]);
        *(float4*)(W2 + ((size_t)b * 1024 + h * 64 + tr * 4 + i) * 1024 + nb * 64 + tc * 4) = o;
    }
}

// ============================================================
extern "C" void kernel_launch(void* const* d_in, const int* in_sizes, int n_in,
                              void* d_out, int out_size)
{
    (void)in_sizes; (void)n_in; (void)out_size;
    const float* x    = (const float*)d_in[0];
    const float* Wq   = (const float*)d_in[1];
    const float* Wkv  = (const float*)d_in[2];
    const float* Wlin = (const float*)d_in[3];
    const float* blin = (const float*)d_in[4];
    float* out = (float*)d_out;

    cudaFuncSetAttribute(gemm_mma<0>, cudaFuncAttributeMaxDynamicSharedMemorySize, SMEM_GEMM);
    cudaFuncSetAttribute(gemm_mma<1>, cudaFuncAttributeMaxDynamicSharedMemorySize, SMEM_GEMM);
    cudaFuncSetAttribute(gemm_mma<2>, cudaFuncAttributeMaxDynamicSharedMemorySize, SMEM_GEMM);

    __half *pxh, *pWq, *pWkv, *pEQ, *pYkv, *pQ, *pW2t;
    float *pzp, *pZ, *pctxp, *pctx, *pW2;
    cudaGetSymbolAddress((void**)&pxh,  g_xh);
    cudaGetSymbolAddress((void**)&pWq,  g_Wqt);
    cudaGetSymbolAddress((void**)&pWkv, g_Wkvt);
    cudaGetSymbolAddress((void**)&pEQ,  g_EQ);   cudaGetSymbolAddress((void**)&pYkv, g_Ykv);
    cudaGetSymbolAddress((void**)&pQ,   g_Q);
    cudaGetSymbolAddress((void**)&pzp,  g_zp);   cudaGetSymbolAddress((void**)&pZ,   g_Z);
    cudaGetSymbolAddress((void**)&pctxp,g_ctxp); cudaGetSymbolAddress((void**)&pctx, g_ctx);
    cudaGetSymbolAddress((void**)&pW2,  g_W2);   cudaGetSymbolAddress((void**)&pW2t, g_W2t);

    dim3 blk(256);

    // 1) conversions
    x_to_h<<<(M_*D_/4)/256, blk>>>((const float4*)x, pxh, (size_t)M_*D_/4);
    transW_h<<<dim3(32, 32, 1), blk>>>(Wq,  pWq,  D_, D_);
    transW_h<<<dim3(64, 32, 1), blk>>>(Wkv, pWkv, D_, 2*D_);

    // 2) projections; exp fused in epilogue
    gemm_mma<1><<<dim3(D_/128, M_/128, 1), blk, SMEM_GEMM>>>(
        (const uint4*)pxh, (const uint4*)pWq,
        pEQ, M_, D_, D_, 0, 0, 0, nullptr);
    gemm_mma<2><<<dim3(2*D_/128, M_/128, 1), blk, SMEM_GEMM>>>(
        (const uint4*)pxh, (const uint4*)pWkv,
        pYkv, M_, 2*D_, D_, 0, 0, 0, nullptr);

    // 3) Q normalize
    qnorm<<<(M_*H_)/8, blk>>>((const __half2*)pEQ, (__half2*)pQ);

    // 4) ctx on tensor cores + Z column sums
    ctx_mma<<<dim3(B_*H_, NSPLIT), dim3(128)>>>(pYkv, pctxp);
    zsum<<<dim3(B_*H_, NSPLIT), blk>>>(pYkv, pzp);
    zred_kernel<<<B_*H_, 64>>>(pzp, pZ);
    ctx_reduce_kernel<<<(B_*H_*64*64)/256, blk>>>(pctxp, pZ, pctx);

    // 5) W2 = ctx @ Wlin (per head), then transpose
    w2_kernel<<<dim3(B_*H_, 16), blk>>>(pctx, Wlin, pW2);
    transW_h<<<dim3(32, 32, B_), blk>>>(pW2, pW2t, D_, D_);

    // 6) out[b] = Q[b] @ W2[b] + blin
    gemm_mma<0><<<dim3(D_/128, S_/128, B_), blk, SMEM_GEMM>>>(
        (const uint4*)pQ, (const uint4*)pW2t,
        out, S_, D_, D_,
        (size_t)S_*D_/8, (size_t)D_*D_/8, (size_t)S_*D_,
        blin);
}